// round 1
// baseline (speedup 1.0000x reference)
#include <cuda_runtime.h>
#include <math.h>

#define NTOK 16384      // B*T
#define Dm   1024
#define Hm   4096
#define Em   8
#define LSm  1824
#define MAXROWS 33280   // 520 * 64  (32768 assignments + per-expert 64-pad)
#define MAXTILES 520

// ---- device scratch (no allocations allowed) ----
__device__ int   g_cnt[Em];
__device__ int   g_off[Em + 1];
__device__ int   g_cursor[Em];
__device__ int   g_top_e[NTOK * 2];
__device__ float g_top_g[NTOK * 2];
__device__ int   g_row_tok[MAXROWS];
__device__ float g_row_gate[MAXROWS];
__device__ float g_h[(size_t)MAXROWS * Hm];   // ~545 MB

// ---------------------------------------------------------------------------
// init: zero expert counters and the `out` region of d_out
// ---------------------------------------------------------------------------
__global__ void init_kernel(float* __restrict__ out) {
    if (blockIdx.x == 0 && threadIdx.x < Em) g_cnt[threadIdx.x] = 0;
    float4 z = make_float4(0.f, 0.f, 0.f, 0.f);
    float4* o4 = (float4*)out;
    const int n4 = NTOK * Dm / 4;
    for (int i = blockIdx.x * blockDim.x + threadIdx.x; i < n4;
         i += gridDim.x * blockDim.x)
        o4[i] = z;
}

// ---------------------------------------------------------------------------
// router: one warp per token. logits = feat @ W_route + b; gate1 = softmax;
// top-2 + renormalized gates; per-expert counts.
// ---------------------------------------------------------------------------
__global__ void router_kernel(const float* __restrict__ x,
                              const int*   __restrict__ city_p,
                              const float* __restrict__ dt,
                              const float* __restrict__ dd,
                              const float* __restrict__ drg,
                              const float* __restrict__ de,
                              const float* __restrict__ cemb,
                              const float* __restrict__ Wr,
                              const float* __restrict__ br,
                              float* __restrict__ gate1) {
    const int warp = threadIdx.x >> 5;
    const int lane = threadIdx.x & 31;
    const int t = blockIdx.x * (blockDim.x >> 5) + warp;
    if (t >= NTOK) return;
    const int city = city_p[0];

    float acc[8];
#pragma unroll
    for (int e = 0; e < 8; e++) acc[e] = 0.f;

    for (int l = lane; l < LSm; l += 32) {
        float f;
        if      (l < 1024) f = x  [(size_t)t * 1024 + l];
        else if (l < 1056) f = cemb[city * 32 + (l - 1024)];
        else if (l < 1312) f = dt [(size_t)t * 256 + (l - 1056)];
        else if (l < 1568) f = dd [(size_t)t * 256 + (l - 1312)];
        else if (l < 1696) f = drg[(size_t)t * 128 + (l - 1568)];
        else               f = de [(size_t)t * 128 + (l - 1696)];
        const float4* w4 = (const float4*)(Wr + (size_t)l * 8);
        float4 w0 = w4[0], w1 = w4[1];
        acc[0] = fmaf(f, w0.x, acc[0]); acc[1] = fmaf(f, w0.y, acc[1]);
        acc[2] = fmaf(f, w0.z, acc[2]); acc[3] = fmaf(f, w0.w, acc[3]);
        acc[4] = fmaf(f, w1.x, acc[4]); acc[5] = fmaf(f, w1.y, acc[5]);
        acc[6] = fmaf(f, w1.z, acc[6]); acc[7] = fmaf(f, w1.w, acc[7]);
    }
#pragma unroll
    for (int e = 0; e < 8; e++)
#pragma unroll
        for (int o = 16; o > 0; o >>= 1)
            acc[e] += __shfl_xor_sync(0xffffffffu, acc[e], o);

    if (lane == 0) {
        float lg[8];
#pragma unroll
        for (int e = 0; e < 8; e++) lg[e] = acc[e] + br[e];
        // dense softmax -> gate1
        float mx = lg[0];
#pragma unroll
        for (int e = 1; e < 8; e++) mx = fmaxf(mx, lg[e]);
        float ex[8], s = 0.f;
#pragma unroll
        for (int e = 0; e < 8; e++) { ex[e] = expf(lg[e] - mx); s += ex[e]; }
        const float inv = 1.f / s;
#pragma unroll
        for (int e = 0; e < 8; e++) gate1[(size_t)t * 8 + e] = ex[e] * inv;
        // top-2 (first occurrence on ties, matching lax.top_k)
        int i0 = 0; float v0 = lg[0];
#pragma unroll
        for (int e = 1; e < 8; e++) if (lg[e] > v0) { v0 = lg[e]; i0 = e; }
        int i1 = -1; float v1 = -1e30f;
#pragma unroll
        for (int e = 0; e < 8; e++)
            if (e != i0 && lg[e] > v1) { v1 = lg[e]; i1 = e; }
        const float e1 = expf(v1 - v0);
        const float g0 = 1.f / (1.f + e1);
        const float g1 = e1 / (1.f + e1);
        g_top_e[t * 2 + 0] = i0; g_top_g[t * 2 + 0] = g0;
        g_top_e[t * 2 + 1] = i1; g_top_g[t * 2 + 1] = g1;
        atomicAdd(&g_cnt[i0], 1);
        atomicAdd(&g_cnt[i1], 1);
    }
}

// ---------------------------------------------------------------------------
// offsets: 64-aligned per-expert segment offsets (single thread, E=8 trivial)
// ---------------------------------------------------------------------------
__global__ void offsets_kernel() {
    int total = 0;
    for (int e = 0; e < Em; e++) {
        g_off[e] = total;
        total += (g_cnt[e] + 63) & ~63;
        g_cursor[e] = 0;
    }
    g_off[Em] = total;
}

// ---------------------------------------------------------------------------
// build: scatter (token, gate) into expert-sorted rows
// ---------------------------------------------------------------------------
__global__ void build_kernel() {
    int t = blockIdx.x * blockDim.x + threadIdx.x;
    if (t >= NTOK) return;
#pragma unroll
    for (int j = 0; j < 2; j++) {
        int e = g_top_e[t * 2 + j];
        int pos = atomicAdd(&g_cursor[e], 1);
        int r = g_off[e] + pos;
        g_row_tok[r]  = t;
        g_row_gate[r] = g_top_g[t * 2 + j];
    }
}

__device__ __forceinline__ float gelu_tanh(float v) {
    float c = v * v * v;
    return 0.5f * v * (1.f + tanhf(0.7978845608028654f * (v + 0.044715f * c)));
}

// ---------------------------------------------------------------------------
// fc: grouped SGEMM  h[r, :] = gelu(x[tok(r)] @ Wfc[e] + bfc[e])
// 64x64x16 tiles, 256 threads, 4x4 microtile
// ---------------------------------------------------------------------------
__global__ void fc_kernel(const float* __restrict__ x,
                          const float* __restrict__ Wfc,
                          const float* __restrict__ bfc) {
    const int row0 = blockIdx.y * 64;
    if (row0 >= g_off[Em]) return;
    int e = 0;
#pragma unroll
    for (int k = 1; k < Em; k++) if (g_off[k] <= row0) e = k;
    const int seg_start = g_off[e];
    const int seg_cnt   = g_cnt[e];
    const int n0 = blockIdx.x * 64;

    __shared__ float As[16][64];
    __shared__ float Bs[16][64];
    __shared__ int   toks[64];

    const int tid = threadIdx.x;
    if (tid < 64) {
        int ml = row0 + tid - seg_start;
        toks[tid] = (ml < seg_cnt) ? g_row_tok[row0 + tid] : -1;
    }
    __syncthreads();

    const float* W = Wfc + (size_t)e * Dm * Hm;
    float acc[4][4];
#pragma unroll
    for (int i = 0; i < 4; i++)
#pragma unroll
        for (int j = 0; j < 4; j++) acc[i][j] = 0.f;

    const int tx = tid & 15, ty = tid >> 4;

    for (int k0 = 0; k0 < Dm; k0 += 16) {
#pragma unroll
        for (int i = 0; i < 4; i++) {
            int idx = tid + i * 256;
            int m = idx >> 4, k = idx & 15;
            int tk = toks[m];
            As[k][m] = (tk >= 0) ? x[(size_t)tk * Dm + k0 + k] : 0.f;
        }
#pragma unroll
        for (int i = 0; i < 4; i++) {
            int idx = tid + i * 256;
            int k = idx >> 6, n = idx & 63;
            Bs[k][n] = W[(size_t)(k0 + k) * Hm + n0 + n];
        }
        __syncthreads();
#pragma unroll
        for (int k = 0; k < 16; k++) {
            float a[4], b[4];
#pragma unroll
            for (int i = 0; i < 4; i++) a[i] = As[k][ty * 4 + i];
#pragma unroll
            for (int j = 0; j < 4; j++) b[j] = Bs[k][tx * 4 + j];
#pragma unroll
            for (int i = 0; i < 4; i++)
#pragma unroll
                for (int j = 0; j < 4; j++)
                    acc[i][j] = fmaf(a[i], b[j], acc[i][j]);
        }
        __syncthreads();
    }

#pragma unroll
    for (int i = 0; i < 4; i++) {
        int m = ty * 4 + i;
        if (toks[m] < 0) continue;
        size_t rbase = (size_t)(row0 + m) * Hm + n0;
#pragma unroll
        for (int j = 0; j < 4; j++) {
            int n = tx * 4 + j;
            float v = acc[i][j] + bfc[e * Hm + n0 + n];
            g_h[rbase + n] = gelu_tanh(v);
        }
    }
}

// ---------------------------------------------------------------------------
// proj: grouped SGEMM  out[tok(r), :] += gate(r) * (h[r] @ Wproj[e] + bproj[e])
// exactly 2 commutative atomicAdds per out element -> deterministic
// ---------------------------------------------------------------------------
__global__ void proj_kernel(const float* __restrict__ Wp,
                            const float* __restrict__ bp,
                            float* __restrict__ out) {
    const int row0 = blockIdx.y * 64;
    if (row0 >= g_off[Em]) return;
    int e = 0;
#pragma unroll
    for (int k = 1; k < Em; k++) if (g_off[k] <= row0) e = k;
    const int seg_start = g_off[e];
    const int seg_cnt   = g_cnt[e];
    const int n0 = blockIdx.x * 64;

    __shared__ float As[16][64];
    __shared__ float Bs[16][64];
    __shared__ int   toks[64];
    __shared__ float gts[64];

    const int tid = threadIdx.x;
    if (tid < 64) {
        int ml = row0 + tid - seg_start;
        bool ok = (ml < seg_cnt);
        toks[tid] = ok ? g_row_tok[row0 + tid] : -1;
        gts[tid]  = ok ? g_row_gate[row0 + tid] : 0.f;
    }
    __syncthreads();

    const float* W = Wp + (size_t)e * Hm * Dm;
    float acc[4][4];
#pragma unroll
    for (int i = 0; i < 4; i++)
#pragma unroll
        for (int j = 0; j < 4; j++) acc[i][j] = 0.f;

    const int tx = tid & 15, ty = tid >> 4;

    for (int k0 = 0; k0 < Hm; k0 += 16) {
#pragma unroll
        for (int i = 0; i < 4; i++) {
            int idx = tid + i * 256;
            int m = idx >> 4, k = idx & 15;
            As[k][m] = (toks[m] >= 0)
                         ? g_h[(size_t)(row0 + m) * Hm + k0 + k] : 0.f;
        }
#pragma unroll
        for (int i = 0; i < 4; i++) {
            int idx = tid + i * 256;
            int k = idx >> 6, n = idx & 63;
            Bs[k][n] = W[(size_t)(k0 + k) * Dm + n0 + n];
        }
        __syncthreads();
#pragma unroll
        for (int k = 0; k < 16; k++) {
            float a[4], b[4];
#pragma unroll
            for (int i = 0; i < 4; i++) a[i] = As[k][ty * 4 + i];
#pragma unroll
            for (int j = 0; j < 4; j++) b[j] = Bs[k][tx * 4 + j];
#pragma unroll
            for (int i = 0; i < 4; i++)
#pragma unroll
                for (int j = 0; j < 4; j++)
                    acc[i][j] = fmaf(a[i], b[j], acc[i][j]);
        }
        __syncthreads();
    }

#pragma unroll
    for (int i = 0; i < 4; i++) {
        int m = ty * 4 + i;
        int tk = toks[m];
        if (tk < 0) continue;
        float g = gts[m];
#pragma unroll
        for (int j = 0; j < 4; j++) {
            int n = tx * 4 + j;
            float v = g * (acc[i][j] + bp[e * Dm + n0 + n]);
            atomicAdd(&out[(size_t)tk * Dm + n0 + n], v);
        }
    }
}

// ---------------------------------------------------------------------------
extern "C" void kernel_launch(void* const* d_in, const int* in_sizes, int n_in,
                              void* d_out, int out_size) {
    const float* x    = (const float*)d_in[0];
    const int*   city = (const int*)  d_in[1];
    const float* dt   = (const float*)d_in[2];
    const float* dd   = (const float*)d_in[3];
    const float* drg  = (const float*)d_in[4];
    const float* de   = (const float*)d_in[5];
    const float* cemb = (const float*)d_in[6];
    const float* Wr   = (const float*)d_in[7];
    const float* br   = (const float*)d_in[8];
    const float* Wfc  = (const float*)d_in[9];
    const float* bfc  = (const float*)d_in[10];
    const float* Wp   = (const float*)d_in[11];
    const float* bp   = (const float*)d_in[12];

    float* out   = (float*)d_out;
    float* gate1 = out + (size_t)NTOK * Dm;

    init_kernel<<<2048, 256>>>(out);
    router_kernel<<<NTOK / 8, 256>>>(x, city, dt, dd, drg, de, cemb, Wr, br, gate1);
    offsets_kernel<<<1, 1>>>();
    build_kernel<<<NTOK / 256, 256>>>();
    fc_kernel  <<<dim3(Hm / 64, MAXTILES), 256>>>(x, Wfc, bfc);
    proj_kernel<<<dim3(Dm / 64, MAXTILES), 256>>>(Wp, bp, out);
}

// round 8
// speedup vs baseline: 2.4581x; 2.4581x over previous
#include <cuda_runtime.h>
#include <cuda_bf16.h>
#include <stdint.h>
#include <math.h>

#define NTOK 16384
#define Dm   1024
#define Hm   4096
#define Em   8
#define LSm  1824
#define MTILE 128
#define MAXROWS 33792        // 264 * 128
#define MAXTILES 264
#define BK 32                // bf16 K per chunk
#define ROWB 80              // 64B data + 16B pad per smem row
#define PLANE_BYTES (128 * ROWB)           // 10240
#define SLOT_BYTES  (4 * PLANE_BYTES)      // 40960 static smem

// ---------------- device scratch (total ~554 MB, matching R1's working size) -
__device__ int   g_cnt[Em];
__device__ int   g_off[Em + 1];
__device__ int   g_cursor[Em];
__device__ int   g_top_e[NTOK * 2];
__device__ float g_top_g[NTOK * 2];
__device__ int   g_row_tok[MAXROWS];
__device__ float g_row_gate[MAXROWS];
__device__ float g_h[(size_t)MAXROWS * Hm];   // fp32 hidden, 553 MB

#define MMA16816(d, a, b) \
    asm volatile("mma.sync.aligned.m16n8k16.row.col.f32.bf16.bf16.f32 " \
        "{%0,%1,%2,%3}, {%4,%5,%6,%7}, {%8,%9}, {%0,%1,%2,%3};" \
        : "+f"((d)[0]), "+f"((d)[1]), "+f"((d)[2]), "+f"((d)[3]) \
        : "r"((a)[0]), "r"((a)[1]), "r"((a)[2]), "r"((a)[3]), \
          "r"((b)[0]), "r"((b)[1]))

__device__ __forceinline__ void split2(float a, float b,
                                       uint32_t& hi, uint32_t& lo) {
    __nv_bfloat16 ha = __float2bfloat16(a), hb = __float2bfloat16(b);
    __nv_bfloat16 la = __float2bfloat16(a - __bfloat162float(ha));
    __nv_bfloat16 lb = __float2bfloat16(b - __bfloat162float(hb));
    __nv_bfloat162 H = __halves2bfloat162(ha, hb);
    __nv_bfloat162 L = __halves2bfloat162(la, lb);
    hi = *(uint32_t*)&H;
    lo = *(uint32_t*)&L;
}

// ---------------------------------------------------------------------------
__global__ void init_kernel(float* __restrict__ out) {
    if (blockIdx.x == 0 && threadIdx.x < Em) g_cnt[threadIdx.x] = 0;
    const int gtid = blockIdx.x * blockDim.x + threadIdx.x;
    for (int i = gtid; i < MAXROWS; i += gridDim.x * blockDim.x) g_row_tok[i] = -1;
    float4 z = make_float4(0.f, 0.f, 0.f, 0.f);
    float4* o4 = (float4*)out;
    const int n4 = NTOK * Dm / 4;
    for (int i = gtid; i < n4; i += gridDim.x * blockDim.x) o4[i] = z;
}

// ---------------------------------------------------------------------------
__global__ void router_kernel(const float* __restrict__ x,
                              const int*   __restrict__ city_p,
                              const float* __restrict__ dt,
                              const float* __restrict__ dd,
                              const float* __restrict__ drg,
                              const float* __restrict__ de,
                              const float* __restrict__ cemb,
                              const float* __restrict__ Wr,
                              const float* __restrict__ br,
                              float* __restrict__ gate1) {
    const int warp = threadIdx.x >> 5;
    const int lane = threadIdx.x & 31;
    const int t = blockIdx.x * (blockDim.x >> 5) + warp;
    if (t >= NTOK) return;
    const int city = city_p[0];

    float acc[8];
#pragma unroll
    for (int e = 0; e < 8; e++) acc[e] = 0.f;

    for (int l = lane; l < LSm; l += 32) {
        float f;
        if      (l < 1024) f = x  [(size_t)t * 1024 + l];
        else if (l < 1056) f = cemb[city * 32 + (l - 1024)];
        else if (l < 1312) f = dt [(size_t)t * 256 + (l - 1056)];
        else if (l < 1568) f = dd [(size_t)t * 256 + (l - 1312)];
        else if (l < 1696) f = drg[(size_t)t * 128 + (l - 1568)];
        else               f = de [(size_t)t * 128 + (l - 1696)];
        const float4* w4 = (const float4*)(Wr + (size_t)l * 8);
        float4 w0 = w4[0], w1 = w4[1];
        acc[0] = fmaf(f, w0.x, acc[0]); acc[1] = fmaf(f, w0.y, acc[1]);
        acc[2] = fmaf(f, w0.z, acc[2]); acc[3] = fmaf(f, w0.w, acc[3]);
        acc[4] = fmaf(f, w1.x, acc[4]); acc[5] = fmaf(f, w1.y, acc[5]);
        acc[6] = fmaf(f, w1.z, acc[6]); acc[7] = fmaf(f, w1.w, acc[7]);
    }
#pragma unroll
    for (int e = 0; e < 8; e++)
#pragma unroll
        for (int o = 16; o > 0; o >>= 1)
            acc[e] += __shfl_xor_sync(0xffffffffu, acc[e], o);

    if (lane == 0) {
        float lg[8];
#pragma unroll
        for (int e = 0; e < 8; e++) lg[e] = acc[e] + br[e];
        float mx = lg[0];
#pragma unroll
        for (int e = 1; e < 8; e++) mx = fmaxf(mx, lg[e]);
        float ex[8], s = 0.f;
#pragma unroll
        for (int e = 0; e < 8; e++) { ex[e] = expf(lg[e] - mx); s += ex[e]; }
        const float inv = 1.f / s;
#pragma unroll
        for (int e = 0; e < 8; e++) gate1[(size_t)t * 8 + e] = ex[e] * inv;
        int i0 = 0; float v0 = lg[0];
#pragma unroll
        for (int e = 1; e < 8; e++) if (lg[e] > v0) { v0 = lg[e]; i0 = e; }
        int i1 = -1; float v1 = -1e30f;
#pragma unroll
        for (int e = 0; e < 8; e++)
            if (e != i0 && lg[e] > v1) { v1 = lg[e]; i1 = e; }
        const float e1 = expf(v1 - v0);
        const float g0 = 1.f / (1.f + e1);
        const float g1 = e1 / (1.f + e1);
        g_top_e[t * 2 + 0] = i0; g_top_g[t * 2 + 0] = g0;
        g_top_e[t * 2 + 1] = i1; g_top_g[t * 2 + 1] = g1;
        atomicAdd(&g_cnt[i0], 1);
        atomicAdd(&g_cnt[i1], 1);
    }
}

// ---------------------------------------------------------------------------
__global__ void offsets_kernel() {
    int total = 0;
    for (int e = 0; e < Em; e++) {
        g_off[e] = total;
        total += (g_cnt[e] + (MTILE - 1)) & ~(MTILE - 1);
        g_cursor[e] = 0;
    }
    g_off[Em] = total;
}

__global__ void build_kernel() {
    int t = blockIdx.x * blockDim.x + threadIdx.x;
    if (t >= NTOK) return;
#pragma unroll
    for (int j = 0; j < 2; j++) {
        int e = g_top_e[t * 2 + j];
        int pos = atomicAdd(&g_cursor[e], 1);
        int r = g_off[e] + pos;
        g_row_tok[r]  = t;
        g_row_gate[r] = g_top_g[t * 2 + j];
    }
}

__device__ __forceinline__ float gelu_tanh(float v) {
    float c = v * v * v;
    return 0.5f * v * (1.f + tanhf(0.7978845608028654f * (v + 0.044715f * c)));
}

// ---------------------------------------------------------------------------
// shared helpers for the two HMMA kernels
// ---------------------------------------------------------------------------
__device__ __forceinline__ void sstore_planes(char* smem, int tid,
                                              const float4* apf,
                                              const float4* bpf0,
                                              const float4* bpf1) {
#pragma unroll
    for (int it = 0; it < 4; it++) {
        const int idx = tid + it * 256;
        const int r = idx >> 3, q = idx & 7;
        uint32_t h0, l0, h1, l1;
        split2(apf[it].x, apf[it].y, h0, l0);
        split2(apf[it].z, apf[it].w, h1, l1);
        *(uint2*)(smem + r * ROWB + q * 8) = make_uint2(h0, h1);
        *(uint2*)(smem + PLANE_BYTES + r * ROWB + q * 8) = make_uint2(l0, l1);
    }
#pragma unroll
    for (int u = 0; u < 2; u++) {
        const int idx = tid + u * 256;
        const int kp = idx >> 5, n4 = idx & 31;
        const float* f0 = (const float*)&bpf0[u];
        const float* f1 = (const float*)&bpf1[u];
#pragma unroll
        for (int j = 0; j < 4; j++) {
            uint32_t h, l;
            split2(f0[j], f1[j], h, l);   // (k even, k odd) pair
            *(uint32_t*)(smem + 2 * PLANE_BYTES + (4 * n4 + j) * ROWB + kp * 4) = h;
            *(uint32_t*)(smem + 3 * PLANE_BYTES + (4 * n4 + j) * ROWB + kp * 4) = l;
        }
    }
}

__device__ __forceinline__ void mma_chunk(const char* smem, int wm, int wn,
                                          int gr, int tc, float (*cacc)[4][4]) {
    const uint32_t* Ah = (const uint32_t*)(smem);
    const uint32_t* Al = (const uint32_t*)(smem + PLANE_BYTES);
    const uint32_t* Bh = (const uint32_t*)(smem + 2 * PLANE_BYTES);
    const uint32_t* Bl = (const uint32_t*)(smem + 3 * PLANE_BYTES);
#pragma unroll
    for (int ks = 0; ks < 2; ks++) {
        const int kb = ks * 8;
        uint32_t bh[4][2], bl[4][2];
#pragma unroll
        for (int nt = 0; nt < 4; nt++) {
            const int n = wn * 32 + nt * 8 + gr;
            bh[nt][0] = Bh[n * 20 + kb + tc];
            bh[nt][1] = Bh[n * 20 + kb + 4 + tc];
            bl[nt][0] = Bl[n * 20 + kb + tc];
            bl[nt][1] = Bl[n * 20 + kb + 4 + tc];
        }
#pragma unroll
        for (int mt = 0; mt < 4; mt++) {
            const int r = wm * 64 + mt * 16 + gr;
            uint32_t ah[4], al[4];
            ah[0] = Ah[r * 20 + kb + tc];
            ah[1] = Ah[(r + 8) * 20 + kb + tc];
            ah[2] = Ah[r * 20 + kb + 4 + tc];
            ah[3] = Ah[(r + 8) * 20 + kb + 4 + tc];
            al[0] = Al[r * 20 + kb + tc];
            al[1] = Al[(r + 8) * 20 + kb + tc];
            al[2] = Al[r * 20 + kb + 4 + tc];
            al[3] = Al[(r + 8) * 20 + kb + 4 + tc];
#pragma unroll
            for (int nt = 0; nt < 4; nt++) {
                MMA16816(cacc[mt][nt], ah, bh[nt]);
                MMA16816(cacc[mt][nt], ah, bl[nt]);
                MMA16816(cacc[mt][nt], al, bh[nt]);
            }
        }
    }
}

// ---------------------------------------------------------------------------
// fc: h[r,:] = gelu(x[tok(r)] @ Wfc[e] + bfc[e])   (fp32 h output)
// ---------------------------------------------------------------------------
__global__ void __launch_bounds__(256, 1)
fc_mma(const float* __restrict__ x, const float* __restrict__ Wfc,
       const float* __restrict__ bfc) {
    const int row0 = blockIdx.y * MTILE;
    if (row0 >= g_off[Em]) return;
    int e = 0;
#pragma unroll
    for (int k = 1; k < Em; k++) if (g_off[k] <= row0) e = k;
    const int n0 = blockIdx.x * 128;

    __shared__ __align__(16) char smem[SLOT_BYTES];
    __shared__ int toks_sm[128];
    const int tid = threadIdx.x;
    const int wid = tid >> 5, lane = tid & 31;
    const int wm = wid & 1, wn = wid >> 1;
    const int gr = lane >> 2, tc = lane & 3;

    if (tid < 128) toks_sm[tid] = g_row_tok[row0 + tid];
    __syncthreads();

    const float* We = Wfc + (size_t)e * Dm * Hm;
    float4 apf[4], bpf0[2], bpf1[2];

    float cacc[4][4][4];
#pragma unroll
    for (int i = 0; i < 4; i++)
#pragma unroll
        for (int j = 0; j < 4; j++)
#pragma unroll
            for (int q = 0; q < 4; q++) cacc[i][j][q] = 0.f;

    const int NC = Dm / BK;
    // prologue load (chunk 0)
    {
        const int k0 = 0;
#pragma unroll
        for (int it = 0; it < 4; it++) {
            const int idx = tid + it * 256, r = idx >> 3, q = idx & 7;
            const int tok = toks_sm[r];
            apf[it] = (tok >= 0)
                ? ((const float4*)(x + (size_t)tok * Dm))[k0 / 4 + q]
                : make_float4(0.f, 0.f, 0.f, 0.f);
        }
#pragma unroll
        for (int u = 0; u < 2; u++) {
            const int idx = tid + u * 256, kp = idx >> 5, n4 = idx & 31;
            const float* bp_ = We + (size_t)(k0 + 2 * kp) * Hm + n0 + 4 * n4;
            bpf0[u] = *(const float4*)bp_;
            bpf1[u] = *(const float4*)(bp_ + Hm);
        }
    }
    sstore_planes(smem, tid, apf, bpf0, bpf1);
    __syncthreads();

    for (int cc = 0; cc < NC; cc++) {
        if (cc + 1 < NC) {
            const int k0 = (cc + 1) * BK;
#pragma unroll
            for (int it = 0; it < 4; it++) {
                const int idx = tid + it * 256, r = idx >> 3, q = idx & 7;
                const int tok = toks_sm[r];
                apf[it] = (tok >= 0)
                    ? ((const float4*)(x + (size_t)tok * Dm))[k0 / 4 + q]
                    : make_float4(0.f, 0.f, 0.f, 0.f);
            }
#pragma unroll
            for (int u = 0; u < 2; u++) {
                const int idx = tid + u * 256, kp = idx >> 5, n4 = idx & 31;
                const float* bp_ = We + (size_t)(k0 + 2 * kp) * Hm + n0 + 4 * n4;
                bpf0[u] = *(const float4*)bp_;
                bpf1[u] = *(const float4*)(bp_ + Hm);
            }
        }
        mma_chunk(smem, wm, wn, gr, tc, cacc);
        __syncthreads();
        if (cc + 1 < NC) {
            sstore_planes(smem, tid, apf, bpf0, bpf1);
            __syncthreads();
        }
    }

    // epilogue: gelu(+bias) -> g_h fp32
    const float* bptr = bfc + (size_t)e * Hm + n0 + wn * 32;
    const int rbase = row0 + wm * 64;
    const int csub = 2 * tc;
#pragma unroll
    for (int mt = 0; mt < 4; mt++) {
        const int r0 = rbase + mt * 16 + gr;
        const int r1 = r0 + 8;
#pragma unroll
        for (int nt = 0; nt < 4; nt++) {
            const int coll = wn * 32 + nt * 8 + csub;
            const float b0 = bptr[nt * 8 + csub];
            const float b1 = bptr[nt * 8 + csub + 1];
            float2 v0 = make_float2(gelu_tanh(cacc[mt][nt][0] + b0),
                                    gelu_tanh(cacc[mt][nt][1] + b1));
            float2 v1 = make_float2(gelu_tanh(cacc[mt][nt][2] + b0),
                                    gelu_tanh(cacc[mt][nt][3] + b1));
            *(float2*)(g_h + (size_t)r0 * Hm + n0 + coll) = v0;
            *(float2*)(g_h + (size_t)r1 * Hm + n0 + coll) = v1;
        }
    }
}

// ---------------------------------------------------------------------------
// proj: out[tok(r),:] += gate(r) * (h[r] @ Wproj[e] + bproj[e])
// ---------------------------------------------------------------------------
__global__ void __launch_bounds__(256, 1)
pj_mma(const float* __restrict__ Wp, const float* __restrict__ bp,
       float* __restrict__ out) {
    const int row0 = blockIdx.y * MTILE;
    if (row0 >= g_off[Em]) return;
    int e = 0;
#pragma unroll
    for (int k = 1; k < Em; k++) if (g_off[k] <= row0) e = k;
    const int n0 = blockIdx.x * 128;

    __shared__ __align__(16) char smem[SLOT_BYTES];
    const int tid = threadIdx.x;
    const int wid = tid >> 5, lane = tid & 31;
    const int wm = wid & 1, wn = wid >> 1;
    const int gr = lane >> 2, tc = lane & 3;

    const float* We = Wp + (size_t)e * Hm * Dm;
    float4 apf[4], bpf0[2], bpf1[2];

    float cacc[4][4][4];
#pragma unroll
    for (int i = 0; i < 4; i++)
#pragma unroll
        for (int j = 0; j < 4; j++)
#pragma unroll
            for (int q = 0; q < 4; q++) cacc[i][j][q] = 0.f;

    const int NC = Hm / BK;
    {
        const int k0 = 0;
#pragma unroll
        for (int it = 0; it < 4; it++) {
            const int idx = tid + it * 256, r = idx >> 3, q = idx & 7;
            apf[it] = *(const float4*)(g_h + (size_t)(row0 + r) * Hm + k0 + q * 4);
        }
#pragma unroll
        for (int u = 0; u < 2; u++) {
            const int idx = tid + u * 256, kp = idx >> 5, n4 = idx & 31;
            const float* bp_ = We + (size_t)(k0 + 2 * kp) * Dm + n0 + 4 * n4;
            bpf0[u] = *(const float4*)bp_;
            bpf1[u] = *(const float4*)(bp_ + Dm);
        }
    }
    sstore_planes(smem, tid, apf, bpf0, bpf1);
    __syncthreads();

    for (int cc = 0; cc < NC; cc++) {
        if (cc + 1 < NC) {
            const int k0 = (cc + 1) * BK;
#pragma unroll
            for (int it = 0; it < 4; it++) {
                const int idx = tid + it * 256, r = idx >> 3, q = idx & 7;
                apf[it] = *(const float4*)(g_h + (size_t)(row0 + r) * Hm + k0 + q * 4);
            }
#pragma unroll
            for (int u = 0; u < 2; u++) {
                const int idx = tid + u * 256, kp = idx >> 5, n4 = idx & 31;
                const float* bp_ = We + (size_t)(k0 + 2 * kp) * Dm + n0 + 4 * n4;
                bpf0[u] = *(const float4*)bp_;
                bpf1[u] = *(const float4*)(bp_ + Dm);
            }
        }
        mma_chunk(smem, wm, wn, gr, tc, cacc);
        __syncthreads();
        if (cc + 1 < NC) {
            sstore_planes(smem, tid, apf, bpf0, bpf1);
            __syncthreads();
        }
    }

    const float* bptr = bp + (size_t)e * Dm + n0 + wn * 32;
    const int rbase = row0 + wm * 64;
    const int csub = 2 * tc;
#pragma unroll
    for (int mt = 0; mt < 4; mt++) {
        const int r0 = rbase + mt * 16 + gr;
        const int r1 = r0 + 8;
#pragma unroll
        for (int nt = 0; nt < 4; nt++) {
            const int coll = wn * 32 + nt * 8 + csub;
            const float b0 = bptr[nt * 8 + csub];
            const float b1 = bptr[nt * 8 + csub + 1];
            const int t0 = g_row_tok[r0];
            const int t1 = g_row_tok[r1];
            if (t0 >= 0) {
                const float g = g_row_gate[r0];
                float* op = out + (size_t)t0 * Dm + n0 + coll;
                atomicAdd(op,     g * (cacc[mt][nt][0] + b0));
                atomicAdd(op + 1, g * (cacc[mt][nt][1] + b1));
            }
            if (t1 >= 0) {
                const float g = g_row_gate[r1];
                float* op = out + (size_t)t1 * Dm + n0 + coll;
                atomicAdd(op,     g * (cacc[mt][nt][2] + b0));
                atomicAdd(op + 1, g * (cacc[mt][nt][3] + b1));
            }
        }
    }
}

// ---------------------------------------------------------------------------
extern "C" void kernel_launch(void* const* d_in, const int* in_sizes, int n_in,
                              void* d_out, int out_size) {
    const float* x    = (const float*)d_in[0];
    const int*   city = (const int*)  d_in[1];
    const float* dt   = (const float*)d_in[2];
    const float* dd   = (const float*)d_in[3];
    const float* drg  = (const float*)d_in[4];
    const float* de   = (const float*)d_in[5];
    const float* cemb = (const float*)d_in[6];
    const float* Wr   = (const float*)d_in[7];
    const float* br   = (const float*)d_in[8];
    const float* Wfc  = (const float*)d_in[9];
    const float* bfc  = (const float*)d_in[10];
    const float* Wp   = (const float*)d_in[11];
    const float* bp   = (const float*)d_in[12];

    float* out   = (float*)d_out;
    float* gate1 = out + (size_t)NTOK * Dm;

    init_kernel<<<2048, 256>>>(out);
    router_kernel<<<NTOK / 8, 256>>>(x, city, dt, dd, drg, de, cemb, Wr, br, gate1);
    offsets_kernel<<<1, 1>>>();
    build_kernel<<<NTOK / 256, 256>>>();
    fc_mma<<<dim3(Hm / 128, MAXTILES), 256>>>(x, Wfc, bfc);
    pj_mma<<<dim3(Dm / 128, MAXTILES), 256>>>(Wp, bp, out);
}

// round 9
// speedup vs baseline: 2.6072x; 1.0607x over previous
#include <cuda_runtime.h>
#include <cuda_bf16.h>
#include <stdint.h>
#include <math.h>

#define NTOK 16384
#define Dm   1024
#define Hm   4096
#define Em   8
#define LSm  1824
#define MTILE 128
#define MAXROWS 33792        // 264 * 128
#define MAXTILES 264
#define BK 32                // bf16 K per chunk
#define ROWB 80              // 64B data + 16B pad per smem row
#define PLANE_BYTES (128 * ROWB)           // 10240
#define SLOT_BYTES  (4 * PLANE_BYTES)      // 40960 static smem

// ---------------- device scratch (~554 MB total, proven safe) ----------------
__device__ int   g_cnt[Em];
__device__ int   g_off[Em + 1];
__device__ int   g_cursor[Em];
__device__ int   g_top_e[NTOK * 2];
__device__ float g_top_g[NTOK * 2];
__device__ int   g_row_tok[MAXROWS];
__device__ float g_row_gate[MAXROWS];
__device__ float g_h[(size_t)MAXROWS * Hm];   // fp32 hidden, 553 MB

#define MMA16816(d, a, b) \
    asm volatile("mma.sync.aligned.m16n8k16.row.col.f32.bf16.bf16.f32 " \
        "{%0,%1,%2,%3}, {%4,%5,%6,%7}, {%8,%9}, {%0,%1,%2,%3};" \
        : "+f"((d)[0]), "+f"((d)[1]), "+f"((d)[2]), "+f"((d)[3]) \
        : "r"((a)[0]), "r"((a)[1]), "r"((a)[2]), "r"((a)[3]), \
          "r"((b)[0]), "r"((b)[1]))

// packed split: one CVT for hi pair, exact reconstruct via <<16, one CVT for lo
__device__ __forceinline__ void split2(float a, float b,
                                       uint32_t& hi, uint32_t& lo) {
    __nv_bfloat162 H = __float22bfloat162_rn(make_float2(a, b));
    uint32_t hbits = *(uint32_t*)&H;
    float ha_f = __uint_as_float(hbits << 16);            // exact bf16->f32
    float hb_f = __uint_as_float(hbits & 0xFFFF0000u);
    __nv_bfloat162 L = __float22bfloat162_rn(make_float2(a - ha_f, b - hb_f));
    hi = hbits;
    lo = *(uint32_t*)&L;
}

// ---------------------------------------------------------------------------
__global__ void init_kernel(float* __restrict__ out) {
    if (blockIdx.x == 0 && threadIdx.x < Em) g_cnt[threadIdx.x] = 0;
    const int gtid = blockIdx.x * blockDim.x + threadIdx.x;
    for (int i = gtid; i < MAXROWS; i += gridDim.x * blockDim.x) g_row_tok[i] = -1;
    float4 z = make_float4(0.f, 0.f, 0.f, 0.f);
    float4* o4 = (float4*)out;
    const int n4 = NTOK * Dm / 4;
    for (int i = gtid; i < n4; i += gridDim.x * blockDim.x) o4[i] = z;
}

// ---------------------------------------------------------------------------
__global__ void router_kernel(const float* __restrict__ x,
                              const int*   __restrict__ city_p,
                              const float* __restrict__ dt,
                              const float* __restrict__ dd,
                              const float* __restrict__ drg,
                              const float* __restrict__ de,
                              const float* __restrict__ cemb,
                              const float* __restrict__ Wr,
                              const float* __restrict__ br,
                              float* __restrict__ gate1) {
    const int warp = threadIdx.x >> 5;
    const int lane = threadIdx.x & 31;
    const int t = blockIdx.x * (blockDim.x >> 5) + warp;
    if (t >= NTOK) return;
    const int city = city_p[0];

    float acc[8];
#pragma unroll
    for (int e = 0; e < 8; e++) acc[e] = 0.f;

    for (int l = lane; l < LSm; l += 32) {
        float f;
        if      (l < 1024) f = x  [(size_t)t * 1024 + l];
        else if (l < 1056) f = cemb[city * 32 + (l - 1024)];
        else if (l < 1312) f = dt [(size_t)t * 256 + (l - 1056)];
        else if (l < 1568) f = dd [(size_t)t * 256 + (l - 1312)];
        else if (l < 1696) f = drg[(size_t)t * 128 + (l - 1568)];
        else               f = de [(size_t)t * 128 + (l - 1696)];
        const float4* w4 = (const float4*)(Wr + (size_t)l * 8);
        float4 w0 = w4[0], w1 = w4[1];
        acc[0] = fmaf(f, w0.x, acc[0]); acc[1] = fmaf(f, w0.y, acc[1]);
        acc[2] = fmaf(f, w0.z, acc[2]); acc[3] = fmaf(f, w0.w, acc[3]);
        acc[4] = fmaf(f, w1.x, acc[4]); acc[5] = fmaf(f, w1.y, acc[5]);
        acc[6] = fmaf(f, w1.z, acc[6]); acc[7] = fmaf(f, w1.w, acc[7]);
    }
#pragma unroll
    for (int e = 0; e < 8; e++)
#pragma unroll
        for (int o = 16; o > 0; o >>= 1)
            acc[e] += __shfl_xor_sync(0xffffffffu, acc[e], o);

    if (lane == 0) {
        float lg[8];
#pragma unroll
        for (int e = 0; e < 8; e++) lg[e] = acc[e] + br[e];
        float mx = lg[0];
#pragma unroll
        for (int e = 1; e < 8; e++) mx = fmaxf(mx, lg[e]);
        float ex[8], s = 0.f;
#pragma unroll
        for (int e = 0; e < 8; e++) { ex[e] = expf(lg[e] - mx); s += ex[e]; }
        const float inv = 1.f / s;
#pragma unroll
        for (int e = 0; e < 8; e++) gate1[(size_t)t * 8 + e] = ex[e] * inv;
        int i0 = 0; float v0 = lg[0];
#pragma unroll
        for (int e = 1; e < 8; e++) if (lg[e] > v0) { v0 = lg[e]; i0 = e; }
        int i1 = -1; float v1 = -1e30f;
#pragma unroll
        for (int e = 0; e < 8; e++)
            if (e != i0 && lg[e] > v1) { v1 = lg[e]; i1 = e; }
        const float e1 = expf(v1 - v0);
        const float g0 = 1.f / (1.f + e1);
        const float g1 = e1 / (1.f + e1);
        g_top_e[t * 2 + 0] = i0; g_top_g[t * 2 + 0] = g0;
        g_top_e[t * 2 + 1] = i1; g_top_g[t * 2 + 1] = g1;
        atomicAdd(&g_cnt[i0], 1);
        atomicAdd(&g_cnt[i1], 1);
    }
}

// ---------------------------------------------------------------------------
__global__ void offsets_kernel() {
    int total = 0;
    for (int e = 0; e < Em; e++) {
        g_off[e] = total;
        total += (g_cnt[e] + (MTILE - 1)) & ~(MTILE - 1);
        g_cursor[e] = 0;
    }
    g_off[Em] = total;
}

__global__ void build_kernel() {
    int t = blockIdx.x * blockDim.x + threadIdx.x;
    if (t >= NTOK) return;
#pragma unroll
    for (int j = 0; j < 2; j++) {
        int e = g_top_e[t * 2 + j];
        int pos = atomicAdd(&g_cursor[e], 1);
        int r = g_off[e] + pos;
        g_row_tok[r]  = t;
        g_row_gate[r] = g_top_g[t * 2 + j];
    }
}

__device__ __forceinline__ float gelu_tanh(float v) {
    float c = v * v * v;
    return 0.5f * v * (1.f + tanhf(0.7978845608028654f * (v + 0.044715f * c)));
}

// ---------------------------------------------------------------------------
__device__ __forceinline__ void sstore_planes(char* smem, int tid,
                                              const float4* apf,
                                              const float4* bpf0,
                                              const float4* bpf1) {
#pragma unroll
    for (int it = 0; it < 4; it++) {
        const int idx = tid + it * 256;
        const int r = idx >> 3, q = idx & 7;
        uint32_t h0, l0, h1, l1;
        split2(apf[it].x, apf[it].y, h0, l0);
        split2(apf[it].z, apf[it].w, h1, l1);
        *(uint2*)(smem + r * ROWB + q * 8) = make_uint2(h0, h1);
        *(uint2*)(smem + PLANE_BYTES + r * ROWB + q * 8) = make_uint2(l0, l1);
    }
#pragma unroll
    for (int u = 0; u < 2; u++) {
        const int idx = tid + u * 256;
        const int kp = idx >> 5, n4 = idx & 31;
        const float* f0 = (const float*)&bpf0[u];
        const float* f1 = (const float*)&bpf1[u];
#pragma unroll
        for (int j = 0; j < 4; j++) {
            uint32_t h, l;
            split2(f0[j], f1[j], h, l);   // (k even, k odd) pair
            *(uint32_t*)(smem + 2 * PLANE_BYTES + (4 * n4 + j) * ROWB + kp * 4) = h;
            *(uint32_t*)(smem + 3 * PLANE_BYTES + (4 * n4 + j) * ROWB + kp * 4) = l;
        }
    }
}

__device__ __forceinline__ void mma_chunk(const char* smem, int wm, int wn,
                                          int gr, int tc, float (*cacc)[4][4]) {
    const uint32_t* Ah = (const uint32_t*)(smem);
    const uint32_t* Al = (const uint32_t*)(smem + PLANE_BYTES);
    const uint32_t* Bh = (const uint32_t*)(smem + 2 * PLANE_BYTES);
    const uint32_t* Bl = (const uint32_t*)(smem + 3 * PLANE_BYTES);
#pragma unroll
    for (int ks = 0; ks < 2; ks++) {
        const int kb = ks * 8;
        uint32_t bh[4][2], bl[4][2];
#pragma unroll
        for (int nt = 0; nt < 4; nt++) {
            const int n = wn * 32 + nt * 8 + gr;
            bh[nt][0] = Bh[n * 20 + kb + tc];
            bh[nt][1] = Bh[n * 20 + kb + 4 + tc];
            bl[nt][0] = Bl[n * 20 + kb + tc];
            bl[nt][1] = Bl[n * 20 + kb + 4 + tc];
        }
#pragma unroll
        for (int mt = 0; mt < 4; mt++) {
            const int r = wm * 64 + mt * 16 + gr;
            uint32_t ah[4], al[4];
            ah[0] = Ah[r * 20 + kb + tc];
            ah[1] = Ah[(r + 8) * 20 + kb + tc];
            ah[2] = Ah[r * 20 + kb + 4 + tc];
            ah[3] = Ah[(r + 8) * 20 + kb + 4 + tc];
            al[0] = Al[r * 20 + kb + tc];
            al[1] = Al[(r + 8) * 20 + kb + tc];
            al[2] = Al[r * 20 + kb + 4 + tc];
            al[3] = Al[(r + 8) * 20 + kb + 4 + tc];
#pragma unroll
            for (int nt = 0; nt < 4; nt++) {
                MMA16816(cacc[mt][nt], ah, bh[nt]);
                MMA16816(cacc[mt][nt], ah, bl[nt]);
                MMA16816(cacc[mt][nt], al, bh[nt]);
            }
        }
    }
}

// ---------------------------------------------------------------------------
// fc: h[r,:] = gelu(x[tok(r)] @ Wfc[e] + bfc[e])   (fp32 h output)
// ---------------------------------------------------------------------------
__global__ void __launch_bounds__(256, 2)
fc_mma(const float* __restrict__ x, const float* __restrict__ Wfc,
       const float* __restrict__ bfc) {
    const int row0 = blockIdx.y * MTILE;
    if (row0 >= g_off[Em]) return;
    int e = 0;
#pragma unroll
    for (int k = 1; k < Em; k++) if (g_off[k] <= row0) e = k;
    const int n0 = blockIdx.x * 128;

    __shared__ __align__(16) char smem[SLOT_BYTES];
    __shared__ int toks_sm[128];
    const int tid = threadIdx.x;
    const int wid = tid >> 5, lane = tid & 31;
    const int wm = wid & 1, wn = wid >> 1;
    const int gr = lane >> 2, tc = lane & 3;

    if (tid < 128) toks_sm[tid] = g_row_tok[row0 + tid];
    __syncthreads();

    const float* We = Wfc + (size_t)e * Dm * Hm;
    float4 apf[4], bpf0[2], bpf1[2];

    float cacc[4][4][4];
#pragma unroll
    for (int i = 0; i < 4; i++)
#pragma unroll
        for (int j = 0; j < 4; j++)
#pragma unroll
            for (int q = 0; q < 4; q++) cacc[i][j][q] = 0.f;

    const int NC = Dm / BK;
    {
        const int k0 = 0;
#pragma unroll
        for (int it = 0; it < 4; it++) {
            const int idx = tid + it * 256, r = idx >> 3, q = idx & 7;
            const int tok = toks_sm[r];
            apf[it] = (tok >= 0)
                ? ((const float4*)(x + (size_t)tok * Dm))[k0 / 4 + q]
                : make_float4(0.f, 0.f, 0.f, 0.f);
        }
#pragma unroll
        for (int u = 0; u < 2; u++) {
            const int idx = tid + u * 256, kp = idx >> 5, n4 = idx & 31;
            const float* bp_ = We + (size_t)(k0 + 2 * kp) * Hm + n0 + 4 * n4;
            bpf0[u] = *(const float4*)bp_;
            bpf1[u] = *(const float4*)(bp_ + Hm);
        }
    }
    sstore_planes(smem, tid, apf, bpf0, bpf1);
    __syncthreads();

    for (int cc = 0; cc < NC; cc++) {
        if (cc + 1 < NC) {
            const int k0 = (cc + 1) * BK;
#pragma unroll
            for (int it = 0; it < 4; it++) {
                const int idx = tid + it * 256, r = idx >> 3, q = idx & 7;
                const int tok = toks_sm[r];
                apf[it] = (tok >= 0)
                    ? ((const float4*)(x + (size_t)tok * Dm))[k0 / 4 + q]
                    : make_float4(0.f, 0.f, 0.f, 0.f);
            }
#pragma unroll
            for (int u = 0; u < 2; u++) {
                const int idx = tid + u * 256, kp = idx >> 5, n4 = idx & 31;
                const float* bp_ = We + (size_t)(k0 + 2 * kp) * Hm + n0 + 4 * n4;
                bpf0[u] = *(const float4*)bp_;
                bpf1[u] = *(const float4*)(bp_ + Hm);
            }
        }
        mma_chunk(smem, wm, wn, gr, tc, cacc);
        __syncthreads();
        if (cc + 1 < NC) {
            sstore_planes(smem, tid, apf, bpf0, bpf1);
            __syncthreads();
        }
    }

    const float* bptr = bfc + (size_t)e * Hm + n0 + wn * 32;
    const int rbase = row0 + wm * 64;
    const int csub = 2 * tc;
#pragma unroll
    for (int mt = 0; mt < 4; mt++) {
        const int r0 = rbase + mt * 16 + gr;
        const int r1 = r0 + 8;
#pragma unroll
        for (int nt = 0; nt < 4; nt++) {
            const int coll = wn * 32 + nt * 8 + csub;
            const float b0 = bptr[nt * 8 + csub];
            const float b1 = bptr[nt * 8 + csub + 1];
            float2 v0 = make_float2(gelu_tanh(cacc[mt][nt][0] + b0),
                                    gelu_tanh(cacc[mt][nt][1] + b1));
            float2 v1 = make_float2(gelu_tanh(cacc[mt][nt][2] + b0),
                                    gelu_tanh(cacc[mt][nt][3] + b1));
            *(float2*)(g_h + (size_t)r0 * Hm + n0 + coll) = v0;
            *(float2*)(g_h + (size_t)r1 * Hm + n0 + coll) = v1;
        }
    }
}

// ---------------------------------------------------------------------------
// proj: out[tok(r),:] += gate(r) * (h[r] @ Wproj[e] + bproj[e])
// ---------------------------------------------------------------------------
__global__ void __launch_bounds__(256, 2)
pj_mma(const float* __restrict__ Wp, const float* __restrict__ bp,
       float* __restrict__ out) {
    const int row0 = blockIdx.y * MTILE;
    if (row0 >= g_off[Em]) return;
    int e = 0;
#pragma unroll
    for (int k = 1; k < Em; k++) if (g_off[k] <= row0) e = k;
    const int n0 = blockIdx.x * 128;

    __shared__ __align__(16) char smem[SLOT_BYTES];
    const int tid = threadIdx.x;
    const int wid = tid >> 5, lane = tid & 31;
    const int wm = wid & 1, wn = wid >> 1;
    const int gr = lane >> 2, tc = lane & 3;

    const float* We = Wp + (size_t)e * Hm * Dm;
    float4 apf[4], bpf0[2], bpf1[2];

    float cacc[4][4][4];
#pragma unroll
    for (int i = 0; i < 4; i++)
#pragma unroll
        for (int j = 0; j < 4; j++)
#pragma unroll
            for (int q = 0; q < 4; q++) cacc[i][j][q] = 0.f;

    const int NC = Hm / BK;
    {
        const int k0 = 0;
#pragma unroll
        for (int it = 0; it < 4; it++) {
            const int idx = tid + it * 256, r = idx >> 3, q = idx & 7;
            apf[it] = *(const float4*)(g_h + (size_t)(row0 + r) * Hm + k0 + q * 4);
        }
#pragma unroll
        for (int u = 0; u < 2; u++) {
            const int idx = tid + u * 256, kp = idx >> 5, n4 = idx & 31;
            const float* bp_ = We + (size_t)(k0 + 2 * kp) * Dm + n0 + 4 * n4;
            bpf0[u] = *(const float4*)bp_;
            bpf1[u] = *(const float4*)(bp_ + Dm);
        }
    }
    sstore_planes(smem, tid, apf, bpf0, bpf1);
    __syncthreads();

    for (int cc = 0; cc < NC; cc++) {
        if (cc + 1 < NC) {
            const int k0 = (cc + 1) * BK;
#pragma unroll
            for (int it = 0; it < 4; it++) {
                const int idx = tid + it * 256, r = idx >> 3, q = idx & 7;
                apf[it] = *(const float4*)(g_h + (size_t)(row0 + r) * Hm + k0 + q * 4);
            }
#pragma unroll
            for (int u = 0; u < 2; u++) {
                const int idx = tid + u * 256, kp = idx >> 5, n4 = idx & 31;
                const float* bp_ = We + (size_t)(k0 + 2 * kp) * Dm + n0 + 4 * n4;
                bpf0[u] = *(const float4*)bp_;
                bpf1[u] = *(const float4*)(bp_ + Dm);
            }
        }
        mma_chunk(smem, wm, wn, gr, tc, cacc);
        __syncthreads();
        if (cc + 1 < NC) {
            sstore_planes(smem, tid, apf, bpf0, bpf1);
            __syncthreads();
        }
    }

    const float* bptr = bp + (size_t)e * Dm + n0 + wn * 32;
    const int rbase = row0 + wm * 64;
    const int csub = 2 * tc;
#pragma unroll
    for (int mt = 0; mt < 4; mt++) {
        const int r0 = rbase + mt * 16 + gr;
        const int r1 = r0 + 8;
#pragma unroll
        for (int nt = 0; nt < 4; nt++) {
            const int coll = wn * 32 + nt * 8 + csub;
            const float b0 = bptr[nt * 8 + csub];
            const float b1 = bptr[nt * 8 + csub + 1];
            const int t0 = g_row_tok[r0];
            const int t1 = g_row_tok[r1];
            if (t0 >= 0) {
                const float g = g_row_gate[r0];
                float* op = out + (size_t)t0 * Dm + n0 + coll;
                atomicAdd(op,     g * (cacc[mt][nt][0] + b0));
                atomicAdd(op + 1, g * (cacc[mt][nt][1] + b1));
            }
            if (t1 >= 0) {
                const float g = g_row_gate[r1];
                float* op = out + (size_t)t1 * Dm + n0 + coll;
                atomicAdd(op,     g * (cacc[mt][nt][2] + b0));
                atomicAdd(op + 1, g * (cacc[mt][nt][3] + b1));
            }
        }
    }
}

// ---------------------------------------------------------------------------
extern "C" void kernel_launch(void* const* d_in, const int* in_sizes, int n_in,
                              void* d_out, int out_size) {
    const float* x    = (const float*)d_in[0];
    const int*   city = (const int*)  d_in[1];
    const float* dt   = (const float*)d_in[2];
    const float* dd   = (const float*)d_in[3];
    const float* drg  = (const float*)d_in[4];
    const float* de   = (const float*)d_in[5];
    const float* cemb = (const float*)d_in[6];
    const float* Wr   = (const float*)d_in[7];
    const float* br   = (const float*)d_in[8];
    const float* Wfc  = (const float*)d_in[9];
    const float* bfc  = (const float*)d_in[10];
    const float* Wp   = (const float*)d_in[11];
    const float* bp   = (const float*)d_in[12];

    float* out   = (float*)d_out;
    float* gate1 = out + (size_t)NTOK * Dm;

    init_kernel<<<2048, 256>>>(out);
    router_kernel<<<NTOK / 8, 256>>>(x, city, dt, dd, drg, de, cemb, Wr, br, gate1);
    offsets_kernel<<<1, 1>>>();
    build_kernel<<<NTOK / 256, 256>>>();
    fc_mma<<<dim3(Hm / 128, MAXTILES), 256>>>(x, Wfc, bfc);
    pj_mma<<<dim3(Dm / 128, MAXTILES), 256>>>(Wp, bp, out);
}